// round 2
// baseline (speedup 1.0000x reference)
#include <cuda_runtime.h>
#include <cuda_bf16.h>
#include <cstdint>

// ---------------------------------------------------------------------------
// GLA block, fp32 baseline (v2: reduced static scratch via aliasing).
// Shapes: B=4, T=2048, Hs=1024, Dk=512, Dv=1024, I=2816, R=16, H=4,
//         dk=128, dv=256, CHUNK=64, Nc=32, tokens N=8192.
// ---------------------------------------------------------------------------

#define NTOK   8192
#define HS     1024
#define DK     512
#define DV     1024
#define II     2816
#define NH     4
#define DKH    128
#define DVH    256
#define CHK    64
#define NCHK   32
#define STR1   129   // padded smem row stride for 128-wide tiles

// ------------------------- scratch (device globals) ------------------------
// g_h    : h (rmsnorm out), later reused as n (mlp rmsnorm out)
// g_gout : g_out projection, later reused as x2 (attn residual)
// g_o    : attention out, later reused as og (gated out; elementwise in-place)
// g_big  : mlp gate activations, then reused in-place by the up-proj epilogue
__device__ float g_h   [NTOK*HS];
__device__ float g_q   [NTOK*DK];    // q, overwritten with qe by pass1
__device__ float g_k   [NTOK*DK];
__device__ float g_v   [NTOK*DV];
__device__ float g_glog[NTOK*DK];
__device__ float g_gout[NTOK*DV];
__device__ float g_o   [NTOK*DV];
__device__ float g_big [NTOK*II];
__device__ float g_dS  [16*NCHK*DKH*DVH];   // 64 MB
__device__ float g_bl  [16*NCHK*DKH];

// ------------------------------ RMSNorm (D=1024) ---------------------------
__global__ __launch_bounds__(256) void rmsnorm_k(const float* __restrict__ x,
                                                 const float* __restrict__ w,
                                                 float* __restrict__ out)
{
    const int row = blockIdx.x;
    const int tid = threadIdx.x;
    const float4 v = *(const float4*)(x + (size_t)row*HS + tid*4);
    float ss = v.x*v.x + v.y*v.y + v.z*v.z + v.w*v.w;
    #pragma unroll
    for (int o = 16; o; o >>= 1) ss += __shfl_xor_sync(0xffffffffu, ss, o);
    __shared__ float sred[8];
    if ((tid & 31) == 0) sred[tid >> 5] = ss;
    __syncthreads();
    float tot = 0.f;
    #pragma unroll
    for (int i = 0; i < 8; i++) tot += sred[i];
    const float sc = rsqrtf(tot * (1.f/1024.f) + 1e-6f);
    const float4 ww = *(const float4*)(w + tid*4);
    float4 r;
    r.x = v.x*sc*ww.x; r.y = v.y*sc*ww.y; r.z = v.z*sc*ww.z; r.w = v.w*sc*ww.w;
    *(float4*)(out + (size_t)row*HS + tid*4) = r;
}

// ------------------------------- SGEMM 128x128x8 ----------------------------
// C[M,N] = A[M,K] @ B[K,N]; epilogue: 0 none, 1 +X, 2 silu(X)*acc
template<int EPI>
__global__ __launch_bounds__(256, 2) void sgemm_k(const float* __restrict__ A,
                                                  const float* __restrict__ B,
                                                  float* __restrict__ C,
                                                  const float* __restrict__ X,
                                                  int M, int N, int K)
{
    __shared__ float As[8][128];
    __shared__ float Bs[8][128];
    const int bx = blockIdx.x, by = blockIdx.y;
    const int tid = threadIdx.x;
    const int tx = tid & 15, ty = tid >> 4;

    const float* Ab = A + (size_t)by * 128 * K;
    const float* Bb = B + (size_t)bx * 128;

    const int arow  = tid >> 1;
    const int acol4 = (tid & 1) * 4;
    const int brow  = tid >> 5;
    const int bcol4 = (tid & 31) * 4;

    float acc[8][8] = {};

    for (int k0 = 0; k0 < K; k0 += 8) {
        float4 a4 = *(const float4*)(Ab + (size_t)arow*K + k0 + acol4);
        As[acol4+0][arow] = a4.x;
        As[acol4+1][arow] = a4.y;
        As[acol4+2][arow] = a4.z;
        As[acol4+3][arow] = a4.w;
        *(float4*)&Bs[brow][bcol4] = *(const float4*)(Bb + (size_t)(k0+brow)*N + bcol4);
        __syncthreads();
        #pragma unroll
        for (int kk = 0; kk < 8; kk++) {
            float4 a0 = *(const float4*)&As[kk][ty*8];
            float4 a1 = *(const float4*)&As[kk][ty*8+4];
            float4 b0 = *(const float4*)&Bs[kk][tx*8];
            float4 b1 = *(const float4*)&Bs[kk][tx*8+4];
            float ar[8] = {a0.x,a0.y,a0.z,a0.w,a1.x,a1.y,a1.z,a1.w};
            float br[8] = {b0.x,b0.y,b0.z,b0.w,b1.x,b1.y,b1.z,b1.w};
            #pragma unroll
            for (int i = 0; i < 8; i++)
                #pragma unroll
                for (int j = 0; j < 8; j++)
                    acc[i][j] += ar[i]*br[j];
        }
        __syncthreads();
    }

    const size_t row0 = (size_t)by*128 + ty*8;
    const int    col0 = bx*128 + tx*8;
    #pragma unroll
    for (int i = 0; i < 8; i++) {
        const size_t base = (row0+i)*N + col0;
        #pragma unroll
        for (int j = 0; j < 8; j++) {
            float val = acc[i][j];
            if (EPI == 1) val += X[base+j];
            if (EPI == 2) { float g = X[base+j]; val *= g / (1.f + __expf(-g)); }
            C[base+j] = val;
        }
    }
}

// --------------------- glog = logsigmoid(h@Wgk1@Wgk2+b)/16 ------------------
__global__ __launch_bounds__(128) void glog_k(const float* __restrict__ h,
                                              const float* __restrict__ Wgk1,
                                              const float* __restrict__ Wgk2,
                                              const float* __restrict__ bg,
                                              float* __restrict__ glog)
{
    const int row = blockIdx.x, tid = threadIdx.x;
    float r[16];
    #pragma unroll
    for (int j = 0; j < 16; j++) r[j] = 0.f;
    const float* hp = h + (size_t)row*HS;
    for (int k2 = tid; k2 < HS; k2 += 128) {
        const float hv = hp[k2];
        const float4* wp = (const float4*)(Wgk1 + (size_t)k2*16);
        float4 w0 = wp[0], w1 = wp[1], w2 = wp[2], w3 = wp[3];
        r[0]+=hv*w0.x; r[1]+=hv*w0.y; r[2]+=hv*w0.z; r[3]+=hv*w0.w;
        r[4]+=hv*w1.x; r[5]+=hv*w1.y; r[6]+=hv*w1.z; r[7]+=hv*w1.w;
        r[8]+=hv*w2.x; r[9]+=hv*w2.y; r[10]+=hv*w2.z; r[11]+=hv*w2.w;
        r[12]+=hv*w3.x; r[13]+=hv*w3.y; r[14]+=hv*w3.z; r[15]+=hv*w3.w;
    }
    __shared__ float red[16*128];
    #pragma unroll
    for (int j = 0; j < 16; j++) red[j*128 + tid] = r[j];
    __syncthreads();
    for (int off = 64; off >= 1; off >>= 1) {
        if (tid < off) {
            #pragma unroll
            for (int j = 0; j < 16; j++) red[j*128+tid] += red[j*128+tid+off];
        }
        __syncthreads();
    }
    __shared__ float rs[16];
    if (tid < 16) rs[tid] = red[tid*128];
    __syncthreads();
    for (int d = tid; d < DK; d += 128) {
        float z = bg[d];
        #pragma unroll
        for (int j = 0; j < 16; j++) z += rs[j] * Wgk2[j*DK + d];
        const float ls = fminf(z, 0.f) - log1pf(__expf(-fabsf(z)));
        glog[(size_t)row*DK + d] = ls * (1.0f/16.0f);
    }
}

// -------------------- attention pass1: per (b,h,chunk) ----------------------
__global__ __launch_bounds__(256) void gla_pass1(
    const float* __restrict__ q, const float* __restrict__ k,
    const float* __restrict__ v, const float* __restrict__ glog,
    float* __restrict__ qe_out, float* __restrict__ o,
    float* __restrict__ dS, float* __restrict__ blast_out)
{
    extern __shared__ float sm1[];
    float* sb  = sm1;                 // 64*STR1 (cumsum b) -> reused as sA (64*65)
    float* sqe = sb  + 64*STR1;
    float* ske = sqe + 64*STR1;
    float* sv  = ske + 64*STR1;       // 64*256
    float* sbl = sv  + 64*256;        // 128
    float* sA  = sb;

    const int c = blockIdx.x, hh = blockIdx.y, b = blockIdx.z;
    const int tid = threadIdx.x;
    const size_t tokbase = (size_t)b*2048 + (size_t)c*CHK;
    const float scale = 0.088388347648318447f;   // 1/sqrt(128)

    if (tid < 128) {                  // cumsum of glog per column d
        const int d = tid;
        float run = 0.f;
        const float* gp = glog + tokbase*DK + hh*DKH + d;
        for (int i = 0; i < CHK; i++) {
            run += gp[(size_t)i*DK];
            sb[i*STR1 + d] = run;
        }
        sbl[d] = run;
    } else {                          // other half loads v tile
        const int t = tid - 128;
        const float* vp = v + tokbase*DV + hh*DVH;
        for (int idx = t; idx < 64*64; idx += 128) {
            const int i = idx >> 6, e4 = idx & 63;
            *(float4*)&sv[i*256 + e4*4] = *(const float4*)(vp + (size_t)i*DV + e4*4);
        }
    }
    __syncthreads();

    {   // qe = q*exp(b)*scale ; ke = k*exp(-b); also persist qe to global
        const float* qp = q + tokbase*DK + hh*DKH;
        const float* kp = k + tokbase*DK + hh*DKH;
        float* qep = qe_out + tokbase*DK + hh*DKH;
        for (int idx = tid; idx < 64*128; idx += 256) {
            const int i = idx >> 7, d = idx & 127;
            const float bb = sb[i*STR1 + d];
            const float qe = qp[(size_t)i*DK + d] * __expf(bb) * scale;
            const float ke = kp[(size_t)i*DK + d] * __expf(-bb);
            sqe[i*STR1 + d] = qe;
            ske[i*STR1 + d] = ke;
            qep[(size_t)i*DK + d] = qe;
        }
    }
    __syncthreads();

    {   // A[i][j] = sum_d qe[i][d]*ke[j][d], tril mask
        const int tx = tid & 15, ty = tid >> 4;
        const int i0 = ty*4, j0 = tx*4;
        float acc[4][4] = {};
        for (int d = 0; d < 128; d++) {
            float a0[4], b0[4];
            #pragma unroll
            for (int ii = 0; ii < 4; ii++) a0[ii] = sqe[(i0+ii)*STR1 + d];
            #pragma unroll
            for (int jj = 0; jj < 4; jj++) b0[jj] = ske[(j0+jj)*STR1 + d];
            #pragma unroll
            for (int ii = 0; ii < 4; ii++)
                #pragma unroll
                for (int jj = 0; jj < 4; jj++)
                    acc[ii][jj] += a0[ii]*b0[jj];
        }
        #pragma unroll
        for (int ii = 0; ii < 4; ii++)
            #pragma unroll
            for (int jj = 0; jj < 4; jj++)
                sA[(i0+ii)*65 + j0+jj] = (j0+jj <= i0+ii) ? acc[ii][jj] : 0.f;
    }
    __syncthreads();

    {   // o_intra = A @ v  (64x256)
        const int tx = tid & 15, ty = tid >> 4;
        const int i0 = ty*4, e0 = tx*16;
        float acc[4][16] = {};
        for (int j = 0; j < 64; j++) {
            float vv[16];
            #pragma unroll
            for (int q4 = 0; q4 < 4; q4++)
                *(float4*)&vv[q4*4] = *(const float4*)&sv[j*256 + e0 + q4*4];
            float aa[4];
            #pragma unroll
            for (int ii = 0; ii < 4; ii++) aa[ii] = sA[(i0+ii)*65 + j];
            #pragma unroll
            for (int ii = 0; ii < 4; ii++)
                #pragma unroll
                for (int jj = 0; jj < 16; jj++)
                    acc[ii][jj] += aa[ii]*vv[jj];
        }
        float* op = o + tokbase*DV + hh*DVH;
        #pragma unroll
        for (int ii = 0; ii < 4; ii++)
            #pragma unroll
            for (int jj = 0; jj < 16; jj++)
                op[(size_t)(i0+ii)*DV + e0 + jj] = acc[ii][jj];
    }

    {   // dS[d][e] = exp(blast[d]) * sum_i ke[i][d]*v[i][e]
        const int tx = tid & 15, ty = tid >> 4;
        const int d0 = ty*8;
        const size_t dbase = (((size_t)(b*NH + hh))*NCHK + c) * (DKH*DVH);
        #pragma unroll
        for (int half = 0; half < 2; half++) {
            const int e0 = tx*16 + half*8;
            float acc[8][8] = {};
            for (int i = 0; i < 64; i++) {
                float kk[8], vv[8];
                #pragma unroll
                for (int dd = 0; dd < 8; dd++) kk[dd] = ske[i*STR1 + d0 + dd];
                *(float4*)&vv[0] = *(const float4*)&sv[i*256 + e0];
                *(float4*)&vv[4] = *(const float4*)&sv[i*256 + e0 + 4];
                #pragma unroll
                for (int dd = 0; dd < 8; dd++)
                    #pragma unroll
                    for (int jj = 0; jj < 8; jj++)
                        acc[dd][jj] += kk[dd]*vv[jj];
            }
            #pragma unroll
            for (int dd = 0; dd < 8; dd++) {
                const float sc = __expf(sbl[d0+dd]);
                #pragma unroll
                for (int jj = 0; jj < 8; jj++)
                    dS[dbase + (size_t)(d0+dd)*DVH + e0 + jj] = acc[dd][jj]*sc;
            }
        }
    }
    if (tid < 128)
        blast_out[(((size_t)(b*NH + hh))*NCHK + c)*DKH + tid] = sbl[tid];
}

// ------- attention pass2: sequential scan, (b,h, dv-slice of 32) -----------
__global__ __launch_bounds__(256) void gla_pass2(
    const float* __restrict__ qe, const float* __restrict__ dS,
    const float* __restrict__ blast, float* __restrict__ o)
{
    extern __shared__ float sm2[];
    float* S   = sm2;               // 128 * 33 (32 cols + pad)
    float* sq  = S + 128*33;        // 64 * STR1
    float* sbl = sq + 64*STR1;      // 128

    const int es = blockIdx.x;      // 0..7 -> dv cols [es*32, es*32+32)
    const int hh = blockIdx.y, b = blockIdx.z;
    const int tid = threadIdx.x;
    const size_t bh = (size_t)b*NH + hh;

    for (int idx = tid; idx < 128*33; idx += 256) S[idx] = 0.f;
    __syncthreads();

    for (int c = 0; c < NCHK; c++) {
        const size_t tokbase = (size_t)b*2048 + (size_t)c*CHK;
        const float* qp = qe + tokbase*DK + hh*DKH;
        for (int idx = tid; idx < 64*32; idx += 256) {
            const int i = idx >> 5, d4 = idx & 31;
            float4 qv = *(const float4*)(qp + (size_t)i*DK + d4*4);
            const int s = i*STR1 + d4*4;
            sq[s] = qv.x; sq[s+1] = qv.y; sq[s+2] = qv.z; sq[s+3] = qv.w;
        }
        if (tid < 128) sbl[tid] = blast[(bh*NCHK + c)*DKH + tid];
        __syncthreads();

        {   // o_inter slice: (64 x 32) = qe_chunk @ S
            const int tx = tid & 7, ty = tid >> 3;
            const int i0 = ty*2, e0 = tx*4;
            float acc[2][4] = {};
            for (int d = 0; d < 128; d++) {
                float s0[4];
                #pragma unroll
                for (int jj = 0; jj < 4; jj++) s0[jj] = S[d*33 + e0 + jj];
                const float q0 = sq[i0*STR1 + d];
                const float q1 = sq[(i0+1)*STR1 + d];
                #pragma unroll
                for (int jj = 0; jj < 4; jj++) {
                    acc[0][jj] += q0*s0[jj];
                    acc[1][jj] += q1*s0[jj];
                }
            }
            float* op = o + tokbase*DV + hh*DVH + es*32;
            #pragma unroll
            for (int ii = 0; ii < 2; ii++)
                #pragma unroll
                for (int jj = 0; jj < 4; jj++)
                    op[(size_t)(i0+ii)*DV + e0 + jj] += acc[ii][jj];
        }
        __syncthreads();

        {   // S = S*exp(blast) + dS_chunk
            const size_t dbase = (bh*NCHK + c)*(size_t)(DKH*DVH) + es*32;
            for (int idx = tid; idx < 128*32; idx += 256) {
                const int d = idx >> 5, e = idx & 31;
                S[d*33 + e] = S[d*33 + e]*__expf(sbl[d]) + dS[dbase + (size_t)d*DVH + e];
            }
        }
        __syncthreads();
    }
}

// --------- output gating: og = rms(o, gnorm_w) * silu(g_out) ---------------
// Safe for og == o (each thread reads its own 4 elements before writing them).
__global__ __launch_bounds__(64) void gate_k(const float* __restrict__ o,
                                             const float* __restrict__ gout,
                                             const float* __restrict__ gw,
                                             float* __restrict__ og)
{
    const int bid = blockIdx.x;          // token*4 + head
    const int tok = bid >> 2, hh = bid & 3;
    const int tid = threadIdx.x;
    const size_t base = (size_t)tok*DV + hh*DVH;

    const float4 x = *(const float4*)(o + base + tid*4);
    float ss = x.x*x.x + x.y*x.y + x.z*x.z + x.w*x.w;
    #pragma unroll
    for (int off = 16; off; off >>= 1) ss += __shfl_xor_sync(0xffffffffu, ss, off);
    __shared__ float s2[2];
    if ((tid & 31) == 0) s2[tid >> 5] = ss;
    __syncthreads();
    ss = s2[0] + s2[1];
    const float sc = rsqrtf(ss * (1.f/256.f) + 1e-6f);

    const float4 g = *(const float4*)(gout + base + tid*4);
    const float4 w = *(const float4*)(gw + tid*4);
    float4 r;
    r.x = x.x*sc*w.x * (g.x / (1.f + __expf(-g.x)));
    r.y = x.y*sc*w.y * (g.y / (1.f + __expf(-g.y)));
    r.z = x.z*sc*w.z * (g.z / (1.f + __expf(-g.z)));
    r.w = x.w*sc*w.w * (g.w / (1.f + __expf(-g.w)));
    *(float4*)(og + base + tid*4) = r;
}

// ------------------------------- launcher ----------------------------------
extern "C" void kernel_launch(void* const* d_in, const int* in_sizes, int n_in,
                              void* d_out, int out_size)
{
    const float* x       = (const float*)d_in[0];
    const float* attn_w  = (const float*)d_in[1];
    const float* Wq      = (const float*)d_in[2];
    const float* Wk      = (const float*)d_in[3];
    const float* Wv      = (const float*)d_in[4];
    const float* Wg      = (const float*)d_in[5];
    const float* Wgk1    = (const float*)d_in[6];
    const float* Wgk2    = (const float*)d_in[7];
    const float* bgk2    = (const float*)d_in[8];
    const float* gnormw  = (const float*)d_in[9];
    const float* Wo      = (const float*)d_in[10];
    const float* mlpnw   = (const float*)d_in[11];
    const float* Wgate   = (const float*)d_in[12];
    const float* Wup     = (const float*)d_in[13];
    const float* Wdown   = (const float*)d_in[14];
    float* out = (float*)d_out;

    float *p_h, *p_q, *p_k, *p_v, *p_glog, *p_gout, *p_o, *p_big, *p_dS, *p_bl;
    cudaGetSymbolAddress((void**)&p_h, g_h);
    cudaGetSymbolAddress((void**)&p_q, g_q);
    cudaGetSymbolAddress((void**)&p_k, g_k);
    cudaGetSymbolAddress((void**)&p_v, g_v);
    cudaGetSymbolAddress((void**)&p_glog, g_glog);
    cudaGetSymbolAddress((void**)&p_gout, g_gout);
    cudaGetSymbolAddress((void**)&p_o, g_o);
    cudaGetSymbolAddress((void**)&p_big, g_big);
    cudaGetSymbolAddress((void**)&p_dS, g_dS);
    cudaGetSymbolAddress((void**)&p_bl, g_bl);

    // Aliases (lifetime-disjoint or provably-safe in-place):
    float* p_og   = p_o;      // gate_k in-place
    float* p_x2   = p_gout;   // gout dead after gate_k
    float* p_n    = p_h;      // h dead after projections + glog
    float* p_gate = p_big;
    float* p_act  = p_big;    // up-proj epilogue reads gate[base], writes act[base]

    const int SMEM1 = (3*64*STR1 + 64*256 + 128) * 4;   // 165120
    const int SMEM2 = (128*33 + 64*STR1 + 128) * 4;     // 50432
    cudaFuncSetAttribute(gla_pass1, cudaFuncAttributeMaxDynamicSharedMemorySize, SMEM1);
    cudaFuncSetAttribute(gla_pass2, cudaFuncAttributeMaxDynamicSharedMemorySize, SMEM2);

    // 1. h = rmsnorm(x)
    rmsnorm_k<<<NTOK, 256>>>(x, attn_w, p_h);
    // 2. projections
    sgemm_k<0><<<dim3(DK/128, NTOK/128), 256>>>(p_h, Wq, p_q, nullptr, NTOK, DK, HS);
    sgemm_k<0><<<dim3(DK/128, NTOK/128), 256>>>(p_h, Wk, p_k, nullptr, NTOK, DK, HS);
    sgemm_k<0><<<dim3(DV/128, NTOK/128), 256>>>(p_h, Wv, p_v, nullptr, NTOK, DV, HS);
    sgemm_k<0><<<dim3(DV/128, NTOK/128), 256>>>(p_h, Wg, p_gout, nullptr, NTOK, DV, HS);
    // 3. gate logits
    glog_k<<<NTOK, 128>>>(p_h, Wgk1, Wgk2, bgk2, p_glog);
    // 4. attention
    gla_pass1<<<dim3(NCHK, NH, 4), 256, SMEM1>>>(p_q, p_k, p_v, p_glog,
                                                 p_q, p_o, p_dS, p_bl);
    gla_pass2<<<dim3(8, NH, 4), 256, SMEM2>>>(p_q, p_dS, p_bl, p_o);
    // 5. output gating (in-place on o)
    gate_k<<<NTOK*NH, 64>>>(p_o, p_gout, gnormw, p_og);
    // 6. x2 = og @ Wo + x
    sgemm_k<1><<<dim3(HS/128, NTOK/128), 256>>>(p_og, Wo, p_x2, x, NTOK, HS, DV);
    // 7. MLP
    rmsnorm_k<<<NTOK, 256>>>(p_x2, mlpnw, p_n);
    sgemm_k<0><<<dim3(II/128, NTOK/128), 256>>>(p_n, Wgate, p_gate, nullptr, NTOK, II, HS);
    sgemm_k<2><<<dim3(II/128, NTOK/128), 256>>>(p_n, Wup, p_act, p_gate, NTOK, II, HS);
    sgemm_k<1><<<dim3(HS/128, NTOK/128), 256>>>(p_act, Wdown, out, p_x2, NTOK, HS, II);
}

// round 3
// speedup vs baseline: 2.3106x; 2.3106x over previous
#include <cuda_runtime.h>
#include <cuda_bf16.h>
#include <cstdint>

// ---------------------------------------------------------------------------
// GLA block, v3: GEMMs on tensor cores (tf32 mma.sync), attention fp32.
// Shapes: B=4, T=2048, Hs=1024, Dk=512, Dv=1024, I=2816, R=16, H=4,
//         dk=128, dv=256, CHUNK=64, Nc=32, tokens N=8192.
// ---------------------------------------------------------------------------

#define NTOK   8192
#define HS     1024
#define DK     512
#define DV     1024
#define II     2816
#define NH     4
#define DKH    128
#define DVH    256
#define CHK    64
#define NCHK   32
#define STR1   129

// ------------------------- scratch (device globals) ------------------------
__device__ float g_h   [NTOK*HS];
__device__ float g_q   [NTOK*DK];
__device__ float g_k   [NTOK*DK];
__device__ float g_v   [NTOK*DV];
__device__ float g_glog[NTOK*DK];
__device__ float g_gout[NTOK*DV];
__device__ float g_o   [NTOK*DV];
__device__ float g_big [NTOK*II];
__device__ float g_dS  [16*NCHK*DKH*DVH];
__device__ float g_bl  [16*NCHK*DKH];

// ------------------------------ helpers ------------------------------------
__device__ __forceinline__ uint32_t f2tf32(float f) {
    uint32_t r;
    asm("cvt.rna.tf32.f32 %0, %1;" : "=r"(r) : "f"(f));
    return r;
}

__device__ __forceinline__ void mma_tf32(float* c, const uint32_t* a, const uint32_t* b) {
    asm volatile(
        "mma.sync.aligned.m16n8k8.row.col.f32.tf32.tf32.f32 "
        "{%0,%1,%2,%3}, {%4,%5,%6,%7}, {%8,%9}, {%0,%1,%2,%3};"
        : "+f"(c[0]), "+f"(c[1]), "+f"(c[2]), "+f"(c[3])
        : "r"(a[0]), "r"(a[1]), "r"(a[2]), "r"(a[3]), "r"(b[0]), "r"(b[1]));
}

// ------------------------------ RMSNorm (D=1024) ---------------------------
__global__ __launch_bounds__(256) void rmsnorm_k(const float* __restrict__ x,
                                                 const float* __restrict__ w,
                                                 float* __restrict__ out)
{
    const int row = blockIdx.x;
    const int tid = threadIdx.x;
    const float4 v = *(const float4*)(x + (size_t)row*HS + tid*4);
    float ss = v.x*v.x + v.y*v.y + v.z*v.z + v.w*v.w;
    #pragma unroll
    for (int o = 16; o; o >>= 1) ss += __shfl_xor_sync(0xffffffffu, ss, o);
    __shared__ float sred[8];
    if ((tid & 31) == 0) sred[tid >> 5] = ss;
    __syncthreads();
    float tot = 0.f;
    #pragma unroll
    for (int i = 0; i < 8; i++) tot += sred[i];
    const float sc = rsqrtf(tot * (1.f/1024.f) + 1e-6f);
    const float4 ww = *(const float4*)(w + tid*4);
    float4 r;
    r.x = v.x*sc*ww.x; r.y = v.y*sc*ww.y; r.z = v.z*sc*ww.z; r.w = v.w*sc*ww.w;
    *(float4*)(out + (size_t)row*HS + tid*4) = r;
}

// ----------------------- tf32 tensor-core GEMM -----------------------------
// C[M,N] = A[M,K] @ B[K,N]; epilogue: 0 none, 1 +X, 2 silu(X)*acc
// 128x128x16 CTA tile, 8 warps (2x4), warp tile 64x32, m16n8k8.
#define ASTR 20    // A smem row stride (floats): banks (20g+kc)%32 distinct
#define BSTR 136   // B smem row stride (floats): banks (8kc+g)%32 distinct

template<int EPI>
__global__ __launch_bounds__(256, 2) void tgemm_k(const float* __restrict__ A,
                                                  const float* __restrict__ B,
                                                  float* __restrict__ C,
                                                  const float* __restrict__ X,
                                                  int M, int N, int K)
{
    __shared__ uint32_t As[128*ASTR];
    __shared__ uint32_t Bs[16*BSTR];

    const int tid  = threadIdx.x;
    const int lane = tid & 31, wid = tid >> 5;
    const int wr = wid >> 2, wc = wid & 3;         // warp grid 2x4
    const int g = lane >> 2, kc = lane & 3;        // fragment coords
    const int bx = blockIdx.x, by = blockIdx.y;

    const float* Ab = A + (size_t)by*128*K;
    const float* Bb = B + (size_t)bx*128;

    // global-load assignments (two float4 each for A and B)
    const int ar0 = tid >> 2, ac0 = (tid & 3)*4;   // A rows ar0, ar0+64
    const int br0 = tid >> 5, bc0 = (tid & 31)*4;  // B rows br0, br0+8

    float4 pa0, pa1, pb0, pb1;
    pa0 = *(const float4*)(Ab + (size_t)ar0*K + ac0);
    pa1 = *(const float4*)(Ab + (size_t)(ar0+64)*K + ac0);
    pb0 = *(const float4*)(Bb + (size_t)br0*N + bc0);
    pb1 = *(const float4*)(Bb + (size_t)(br0+8)*N + bc0);

    float acc[4][4][4];
    #pragma unroll
    for (int i = 0; i < 4; i++)
        #pragma unroll
        for (int j = 0; j < 4; j++)
            #pragma unroll
            for (int t = 0; t < 4; t++) acc[i][j][t] = 0.f;

    for (int kt = 0; kt < K; kt += 16) {
        // commit prefetched tile to smem (tf32-converted)
        {
            uint4 u;
            u.x=f2tf32(pa0.x); u.y=f2tf32(pa0.y); u.z=f2tf32(pa0.z); u.w=f2tf32(pa0.w);
            *(uint4*)&As[ar0*ASTR + ac0] = u;
            u.x=f2tf32(pa1.x); u.y=f2tf32(pa1.y); u.z=f2tf32(pa1.z); u.w=f2tf32(pa1.w);
            *(uint4*)&As[(ar0+64)*ASTR + ac0] = u;
            u.x=f2tf32(pb0.x); u.y=f2tf32(pb0.y); u.z=f2tf32(pb0.z); u.w=f2tf32(pb0.w);
            *(uint4*)&Bs[br0*BSTR + bc0] = u;
            u.x=f2tf32(pb1.x); u.y=f2tf32(pb1.y); u.z=f2tf32(pb1.z); u.w=f2tf32(pb1.w);
            *(uint4*)&Bs[(br0+8)*BSTR + bc0] = u;
        }
        __syncthreads();

        if (kt + 16 < K) {   // prefetch next tile into registers
            pa0 = *(const float4*)(Ab + (size_t)ar0*K + kt+16 + ac0);
            pa1 = *(const float4*)(Ab + (size_t)(ar0+64)*K + kt+16 + ac0);
            pb0 = *(const float4*)(Bb + (size_t)(kt+16+br0)*N + bc0);
            pb1 = *(const float4*)(Bb + (size_t)(kt+16+br0+8)*N + bc0);
        }

        #pragma unroll
        for (int ks = 0; ks < 2; ks++) {
            const int k0 = ks*8;
            uint32_t af[4][4], bf[4][2];
            #pragma unroll
            for (int mi = 0; mi < 4; mi++) {
                const int m0 = wr*64 + mi*16;
                af[mi][0] = As[(m0+g  )*ASTR + k0+kc  ];
                af[mi][1] = As[(m0+g+8)*ASTR + k0+kc  ];
                af[mi][2] = As[(m0+g  )*ASTR + k0+kc+4];
                af[mi][3] = As[(m0+g+8)*ASTR + k0+kc+4];
            }
            #pragma unroll
            for (int nj = 0; nj < 4; nj++) {
                const int n0 = wc*32 + nj*8;
                bf[nj][0] = Bs[(k0+kc  )*BSTR + n0+g];
                bf[nj][1] = Bs[(k0+kc+4)*BSTR + n0+g];
            }
            #pragma unroll
            for (int mi = 0; mi < 4; mi++)
                #pragma unroll
                for (int nj = 0; nj < 4; nj++)
                    mma_tf32(acc[mi][nj], af[mi], bf[nj]);
        }
        __syncthreads();
    }

    // ------------------------------ epilogue -------------------------------
    const int cp = (lane & 3)*2;     // column pair within 8-wide n-tile
    #pragma unroll
    for (int mi = 0; mi < 4; mi++) {
        #pragma unroll
        for (int rh = 0; rh < 2; rh++) {           // row g / row g+8
            const size_t row = (size_t)by*128 + wr*64 + mi*16 + g + rh*8;
            #pragma unroll
            for (int nj = 0; nj < 4; nj++) {
                const size_t col = (size_t)bx*128 + wc*32 + nj*8 + cp;
                const size_t idx = row*N + col;
                float v0 = acc[mi][nj][rh*2+0];
                float v1 = acc[mi][nj][rh*2+1];
                if (EPI == 1) { v0 += X[idx]; v1 += X[idx+1]; }
                if (EPI == 2) {
                    float g0 = X[idx], g1 = X[idx+1];
                    v0 *= g0 / (1.f + __expf(-g0));
                    v1 *= g1 / (1.f + __expf(-g1));
                }
                float2 st; st.x = v0; st.y = v1;
                *(float2*)(C + idx) = st;
            }
        }
    }
}

// --------------------- glog = logsigmoid(h@Wgk1@Wgk2+b)/16 ------------------
__global__ __launch_bounds__(128) void glog_k(const float* __restrict__ h,
                                              const float* __restrict__ Wgk1,
                                              const float* __restrict__ Wgk2,
                                              const float* __restrict__ bg,
                                              float* __restrict__ glog)
{
    const int row = blockIdx.x, tid = threadIdx.x;
    float r[16];
    #pragma unroll
    for (int j = 0; j < 16; j++) r[j] = 0.f;
    const float* hp = h + (size_t)row*HS;
    for (int k2 = tid; k2 < HS; k2 += 128) {
        const float hv = hp[k2];
        const float4* wp = (const float4*)(Wgk1 + (size_t)k2*16);
        float4 w0 = wp[0], w1 = wp[1], w2 = wp[2], w3 = wp[3];
        r[0]+=hv*w0.x; r[1]+=hv*w0.y; r[2]+=hv*w0.z; r[3]+=hv*w0.w;
        r[4]+=hv*w1.x; r[5]+=hv*w1.y; r[6]+=hv*w1.z; r[7]+=hv*w1.w;
        r[8]+=hv*w2.x; r[9]+=hv*w2.y; r[10]+=hv*w2.z; r[11]+=hv*w2.w;
        r[12]+=hv*w3.x; r[13]+=hv*w3.y; r[14]+=hv*w3.z; r[15]+=hv*w3.w;
    }
    __shared__ float red[16*128];
    #pragma unroll
    for (int j = 0; j < 16; j++) red[j*128 + tid] = r[j];
    __syncthreads();
    for (int off = 64; off >= 1; off >>= 1) {
        if (tid < off) {
            #pragma unroll
            for (int j = 0; j < 16; j++) red[j*128+tid] += red[j*128+tid+off];
        }
        __syncthreads();
    }
    __shared__ float rs[16];
    if (tid < 16) rs[tid] = red[tid*128];
    __syncthreads();
    for (int d = tid; d < DK; d += 128) {
        float z = bg[d];
        #pragma unroll
        for (int j = 0; j < 16; j++) z += rs[j] * Wgk2[j*DK + d];
        const float ls = fminf(z, 0.f) - log1pf(__expf(-fabsf(z)));
        glog[(size_t)row*DK + d] = ls * (1.0f/16.0f);
    }
}

// -------------------- attention pass1: per (b,h,chunk) ----------------------
__global__ __launch_bounds__(256) void gla_pass1(
    const float* __restrict__ q, const float* __restrict__ k,
    const float* __restrict__ v, const float* __restrict__ glog,
    float* __restrict__ qe_out, float* __restrict__ o,
    float* __restrict__ dS, float* __restrict__ blast_out)
{
    extern __shared__ float sm1[];
    float* sb  = sm1;
    float* sqe = sb  + 64*STR1;
    float* ske = sqe + 64*STR1;
    float* sv  = ske + 64*STR1;
    float* sbl = sv  + 64*256;
    float* sA  = sb;

    const int c = blockIdx.x, hh = blockIdx.y, b = blockIdx.z;
    const int tid = threadIdx.x;
    const size_t tokbase = (size_t)b*2048 + (size_t)c*CHK;
    const float scale = 0.088388347648318447f;

    if (tid < 128) {
        const int d = tid;
        float run = 0.f;
        const float* gp = glog + tokbase*DK + hh*DKH + d;
        for (int i = 0; i < CHK; i++) {
            run += gp[(size_t)i*DK];
            sb[i*STR1 + d] = run;
        }
        sbl[d] = run;
    } else {
        const int t = tid - 128;
        const float* vp = v + tokbase*DV + hh*DVH;
        for (int idx = t; idx < 64*64; idx += 128) {
            const int i = idx >> 6, e4 = idx & 63;
            *(float4*)&sv[i*256 + e4*4] = *(const float4*)(vp + (size_t)i*DV + e4*4);
        }
    }
    __syncthreads();

    {
        const float* qp = q + tokbase*DK + hh*DKH;
        const float* kp = k + tokbase*DK + hh*DKH;
        float* qep = qe_out + tokbase*DK + hh*DKH;
        for (int idx = tid; idx < 64*128; idx += 256) {
            const int i = idx >> 7, d = idx & 127;
            const float bb = sb[i*STR1 + d];
            const float qe = qp[(size_t)i*DK + d] * __expf(bb) * scale;
            const float ke = kp[(size_t)i*DK + d] * __expf(-bb);
            sqe[i*STR1 + d] = qe;
            ske[i*STR1 + d] = ke;
            qep[(size_t)i*DK + d] = qe;
        }
    }
    __syncthreads();

    {
        const int tx = tid & 15, ty = tid >> 4;
        const int i0 = ty*4, j0 = tx*4;
        float acc[4][4] = {};
        for (int d = 0; d < 128; d++) {
            float a0[4], b0[4];
            #pragma unroll
            for (int ii = 0; ii < 4; ii++) a0[ii] = sqe[(i0+ii)*STR1 + d];
            #pragma unroll
            for (int jj = 0; jj < 4; jj++) b0[jj] = ske[(j0+jj)*STR1 + d];
            #pragma unroll
            for (int ii = 0; ii < 4; ii++)
                #pragma unroll
                for (int jj = 0; jj < 4; jj++)
                    acc[ii][jj] += a0[ii]*b0[jj];
        }
        #pragma unroll
        for (int ii = 0; ii < 4; ii++)
            #pragma unroll
            for (int jj = 0; jj < 4; jj++)
                sA[(i0+ii)*65 + j0+jj] = (j0+jj <= i0+ii) ? acc[ii][jj] : 0.f;
    }
    __syncthreads();

    {
        const int tx = tid & 15, ty = tid >> 4;
        const int i0 = ty*4, e0 = tx*16;
        float acc[4][16] = {};
        for (int j = 0; j < 64; j++) {
            float vv[16];
            #pragma unroll
            for (int q4 = 0; q4 < 4; q4++)
                *(float4*)&vv[q4*4] = *(const float4*)&sv[j*256 + e0 + q4*4];
            float aa[4];
            #pragma unroll
            for (int ii = 0; ii < 4; ii++) aa[ii] = sA[(i0+ii)*65 + j];
            #pragma unroll
            for (int ii = 0; ii < 4; ii++)
                #pragma unroll
                for (int jj = 0; jj < 16; jj++)
                    acc[ii][jj] += aa[ii]*vv[jj];
        }
        float* op = o + tokbase*DV + hh*DVH;
        #pragma unroll
        for (int ii = 0; ii < 4; ii++)
            #pragma unroll
            for (int jj = 0; jj < 16; jj++)
                op[(size_t)(i0+ii)*DV + e0 + jj] = acc[ii][jj];
    }

    {
        const int tx = tid & 15, ty = tid >> 4;
        const int d0 = ty*8;
        const size_t dbase = (((size_t)(b*NH + hh))*NCHK + c) * (DKH*DVH);
        #pragma unroll
        for (int half = 0; half < 2; half++) {
            const int e0 = tx*16 + half*8;
            float acc[8][8] = {};
            for (int i = 0; i < 64; i++) {
                float kk[8], vv[8];
                #pragma unroll
                for (int dd = 0; dd < 8; dd++) kk[dd] = ske[i*STR1 + d0 + dd];
                *(float4*)&vv[0] = *(const float4*)&sv[i*256 + e0];
                *(float4*)&vv[4] = *(const float4*)&sv[i*256 + e0 + 4];
                #pragma unroll
                for (int dd = 0; dd < 8; dd++)
                    #pragma unroll
                    for (int jj = 0; jj < 8; jj++)
                        acc[dd][jj] += kk[dd]*vv[jj];
            }
            #pragma unroll
            for (int dd = 0; dd < 8; dd++) {
                const float sc = __expf(sbl[d0+dd]);
                #pragma unroll
                for (int jj = 0; jj < 8; jj++)
                    dS[dbase + (size_t)(d0+dd)*DVH + e0 + jj] = acc[dd][jj]*sc;
            }
        }
    }
    if (tid < 128)
        blast_out[(((size_t)(b*NH + hh))*NCHK + c)*DKH + tid] = sbl[tid];
}

// ------- attention pass2: sequential scan, (b,h, dv-slice of 32) -----------
__global__ __launch_bounds__(256) void gla_pass2(
    const float* __restrict__ qe, const float* __restrict__ dS,
    const float* __restrict__ blast, float* __restrict__ o)
{
    extern __shared__ float sm2[];
    float* S   = sm2;
    float* sq  = S + 128*33;
    float* sbl = sq + 64*STR1;

    const int es = blockIdx.x;
    const int hh = blockIdx.y, b = blockIdx.z;
    const int tid = threadIdx.x;
    const size_t bh = (size_t)b*NH + hh;

    for (int idx = tid; idx < 128*33; idx += 256) S[idx] = 0.f;
    __syncthreads();

    for (int c = 0; c < NCHK; c++) {
        const size_t tokbase = (size_t)b*2048 + (size_t)c*CHK;
        const float* qp = qe + tokbase*DK + hh*DKH;
        for (int idx = tid; idx < 64*32; idx += 256) {
            const int i = idx >> 5, d4 = idx & 31;
            float4 qv = *(const float4*)(qp + (size_t)i*DK + d4*4);
            const int s = i*STR1 + d4*4;
            sq[s] = qv.x; sq[s+1] = qv.y; sq[s+2] = qv.z; sq[s+3] = qv.w;
        }
        if (tid < 128) sbl[tid] = blast[(bh*NCHK + c)*DKH + tid];
        __syncthreads();

        {
            const int tx = tid & 7, ty = tid >> 3;
            const int i0 = ty*2, e0 = tx*4;
            float acc[2][4] = {};
            for (int d = 0; d < 128; d++) {
                float s0[4];
                #pragma unroll
                for (int jj = 0; jj < 4; jj++) s0[jj] = S[d*33 + e0 + jj];
                const float q0 = sq[i0*STR1 + d];
                const float q1 = sq[(i0+1)*STR1 + d];
                #pragma unroll
                for (int jj = 0; jj < 4; jj++) {
                    acc[0][jj] += q0*s0[jj];
                    acc[1][jj] += q1*s0[jj];
                }
            }
            float* op = o + tokbase*DV + hh*DVH + es*32;
            #pragma unroll
            for (int ii = 0; ii < 2; ii++)
                #pragma unroll
                for (int jj = 0; jj < 4; jj++)
                    op[(size_t)(i0+ii)*DV + e0 + jj] += acc[ii][jj];
        }
        __syncthreads();

        {
            const size_t dbase = (bh*NCHK + c)*(size_t)(DKH*DVH) + es*32;
            for (int idx = tid; idx < 128*32; idx += 256) {
                const int d = idx >> 5, e = idx & 31;
                S[d*33 + e] = S[d*33 + e]*__expf(sbl[d]) + dS[dbase + (size_t)d*DVH + e];
            }
        }
        __syncthreads();
    }
}

// --------- output gating: og = rms(o, gnorm_w) * silu(g_out) ---------------
__global__ __launch_bounds__(64) void gate_k(const float* __restrict__ o,
                                             const float* __restrict__ gout,
                                             const float* __restrict__ gw,
                                             float* __restrict__ og)
{
    const int bid = blockIdx.x;
    const int tok = bid >> 2, hh = bid & 3;
    const int tid = threadIdx.x;
    const size_t base = (size_t)tok*DV + hh*DVH;

    const float4 x = *(const float4*)(o + base + tid*4);
    float ss = x.x*x.x + x.y*x.y + x.z*x.z + x.w*x.w;
    #pragma unroll
    for (int off = 16; off; off >>= 1) ss += __shfl_xor_sync(0xffffffffu, ss, off);
    __shared__ float s2[2];
    if ((tid & 31) == 0) s2[tid >> 5] = ss;
    __syncthreads();
    ss = s2[0] + s2[1];
    const float sc = rsqrtf(ss * (1.f/256.f) + 1e-6f);

    const float4 g = *(const float4*)(gout + base + tid*4);
    const float4 w = *(const float4*)(gw + tid*4);
    float4 r;
    r.x = x.x*sc*w.x * (g.x / (1.f + __expf(-g.x)));
    r.y = x.y*sc*w.y * (g.y / (1.f + __expf(-g.y)));
    r.z = x.z*sc*w.z * (g.z / (1.f + __expf(-g.z)));
    r.w = x.w*sc*w.w * (g.w / (1.f + __expf(-g.w)));
    *(float4*)(og + base + tid*4) = r;
}

// ------------------------------- launcher ----------------------------------
extern "C" void kernel_launch(void* const* d_in, const int* in_sizes, int n_in,
                              void* d_out, int out_size)
{
    const float* x       = (const float*)d_in[0];
    const float* attn_w  = (const float*)d_in[1];
    const float* Wq      = (const float*)d_in[2];
    const float* Wk      = (const float*)d_in[3];
    const float* Wv      = (const float*)d_in[4];
    const float* Wg      = (const float*)d_in[5];
    const float* Wgk1    = (const float*)d_in[6];
    const float* Wgk2    = (const float*)d_in[7];
    const float* bgk2    = (const float*)d_in[8];
    const float* gnormw  = (const float*)d_in[9];
    const float* Wo      = (const float*)d_in[10];
    const float* mlpnw   = (const float*)d_in[11];
    const float* Wgate   = (const float*)d_in[12];
    const float* Wup     = (const float*)d_in[13];
    const float* Wdown   = (const float*)d_in[14];
    float* out = (float*)d_out;

    float *p_h, *p_q, *p_k, *p_v, *p_glog, *p_gout, *p_o, *p_big, *p_dS, *p_bl;
    cudaGetSymbolAddress((void**)&p_h, g_h);
    cudaGetSymbolAddress((void**)&p_q, g_q);
    cudaGetSymbolAddress((void**)&p_k, g_k);
    cudaGetSymbolAddress((void**)&p_v, g_v);
    cudaGetSymbolAddress((void**)&p_glog, g_glog);
    cudaGetSymbolAddress((void**)&p_gout, g_gout);
    cudaGetSymbolAddress((void**)&p_o, g_o);
    cudaGetSymbolAddress((void**)&p_big, g_big);
    cudaGetSymbolAddress((void**)&p_dS, g_dS);
    cudaGetSymbolAddress((void**)&p_bl, g_bl);

    float* p_og   = p_o;      // gate_k in-place
    float* p_x2   = p_gout;   // gout dead after gate_k
    float* p_n    = p_h;      // h dead after projections + glog
    float* p_gate = p_big;
    float* p_act  = p_big;    // up-proj epilogue reads gate[idx], writes act[idx]

    const int SMEM1 = (3*64*STR1 + 64*256 + 128) * 4;
    const int SMEM2 = (128*33 + 64*STR1 + 128) * 4;
    cudaFuncSetAttribute(gla_pass1, cudaFuncAttributeMaxDynamicSharedMemorySize, SMEM1);
    cudaFuncSetAttribute(gla_pass2, cudaFuncAttributeMaxDynamicSharedMemorySize, SMEM2);

    // 1. h = rmsnorm(x)
    rmsnorm_k<<<NTOK, 256>>>(x, attn_w, p_h);
    // 2. projections (tf32 tensor cores)
    tgemm_k<0><<<dim3(DK/128, NTOK/128), 256>>>(p_h, Wq, p_q, nullptr, NTOK, DK, HS);
    tgemm_k<0><<<dim3(DK/128, NTOK/128), 256>>>(p_h, Wk, p_k, nullptr, NTOK, DK, HS);
    tgemm_k<0><<<dim3(DV/128, NTOK/128), 256>>>(p_h, Wv, p_v, nullptr, NTOK, DV, HS);
    tgemm_k<0><<<dim3(DV/128, NTOK/128), 256>>>(p_h, Wg, p_gout, nullptr, NTOK, DV, HS);
    // 3. gate logits
    glog_k<<<NTOK, 128>>>(p_h, Wgk1, Wgk2, bgk2, p_glog);
    // 4. attention
    gla_pass1<<<dim3(NCHK, NH, 4), 256, SMEM1>>>(p_q, p_k, p_v, p_glog,
                                                 p_q, p_o, p_dS, p_bl);
    gla_pass2<<<dim3(8, NH, 4), 256, SMEM2>>>(p_q, p_dS, p_bl, p_o);
    // 5. output gating (in-place on o)
    gate_k<<<NTOK*NH, 64>>>(p_o, p_gout, gnormw, p_og);
    // 6. x2 = og @ Wo + x
    tgemm_k<1><<<dim3(HS/128, NTOK/128), 256>>>(p_og, Wo, p_x2, x, NTOK, HS, DV);
    // 7. MLP
    rmsnorm_k<<<NTOK, 256>>>(p_x2, mlpnw, p_n);
    tgemm_k<0><<<dim3(II/128, NTOK/128), 256>>>(p_n, Wgate, p_gate, nullptr, NTOK, II, HS);
    tgemm_k<2><<<dim3(II/128, NTOK/128), 256>>>(p_n, Wup, p_act, p_gate, NTOK, II, HS);
    tgemm_k<1><<<dim3(HS/128, NTOK/128), 256>>>(p_act, Wdown, out, p_x2, NTOK, HS, II);
}

// round 5
// speedup vs baseline: 2.7811x; 1.2037x over previous
#include <cuda_runtime.h>
#include <cuda_bf16.h>
#include <cstdint>

// ---------------------------------------------------------------------------
// GLA block, v5: tf32 tensor-core GEMMs with cp.async 3-stage pipeline.
// All GEMM operands pre-rounded to tf32 (RNA) at source; weight copies are
// staged inside g_dS (lifetime-disjoint) so static footprint matches v3.
// ---------------------------------------------------------------------------

#define NTOK   8192
#define HS     1024
#define DK     512
#define DV     1024
#define II     2816
#define NH     4
#define DKH    128
#define DVH    256
#define CHK    64
#define NCHK   32
#define STR1   129

// ------------------------- scratch (device globals) ------------------------
__device__ float g_h   [NTOK*HS];
__device__ float g_q   [NTOK*DK];
__device__ float g_k   [NTOK*DK];
__device__ float g_v   [NTOK*DV];
__device__ float g_glog[NTOK*DK];
__device__ float g_gout[NTOK*DV];
__device__ float g_o   [NTOK*DV];
__device__ float g_big [NTOK*II];
__device__ float g_dS  [16*NCHK*DKH*DVH];   // 16M floats; also stages weights
__device__ float g_bl  [16*NCHK*DKH];

// ------------------------------ helpers ------------------------------------
__device__ __forceinline__ uint32_t f2tf32(float f) {
    uint32_t r;
    asm("cvt.rna.tf32.f32 %0, %1;" : "=r"(r) : "f"(f));
    return r;
}
__device__ __forceinline__ float rtf32(float f) { return __uint_as_float(f2tf32(f)); }

__device__ __forceinline__ void mma_tf32(float* c, const uint32_t* a, const uint32_t* b) {
    asm volatile(
        "mma.sync.aligned.m16n8k8.row.col.f32.tf32.tf32.f32 "
        "{%0,%1,%2,%3}, {%4,%5,%6,%7}, {%8,%9}, {%0,%1,%2,%3};"
        : "+f"(c[0]), "+f"(c[1]), "+f"(c[2]), "+f"(c[3])
        : "r"(a[0]), "r"(a[1]), "r"(a[2]), "r"(a[3]), "r"(b[0]), "r"(b[1]));
}

__device__ __forceinline__ void cpa16(uint32_t saddr, const float* g) {
    asm volatile("cp.async.cg.shared.global [%0], [%1], 16;" :: "r"(saddr), "l"(g));
}
#define CPA_COMMIT() asm volatile("cp.async.commit_group;")
#define CPA_WAIT1()  asm volatile("cp.async.wait_group 1;")

// --------------------- weight tf32 pre-round -------------------------------
__global__ __launch_bounds__(256) void cvtw_k(const float* __restrict__ in,
                                              float* __restrict__ out)
{
    const int i = (blockIdx.x*256 + threadIdx.x)*4;
    float4 v = *(const float4*)(in + i);
    v.x = rtf32(v.x); v.y = rtf32(v.y); v.z = rtf32(v.z); v.w = rtf32(v.w);
    *(float4*)(out + i) = v;
}

// ------------------------------ RMSNorm (D=1024) ---------------------------
__global__ __launch_bounds__(256) void rmsnorm_k(const float* __restrict__ x,
                                                 const float* __restrict__ w,
                                                 float* __restrict__ out)
{
    const int row = blockIdx.x;
    const int tid = threadIdx.x;
    const float4 v = *(const float4*)(x + (size_t)row*HS + tid*4);
    float ss = v.x*v.x + v.y*v.y + v.z*v.z + v.w*v.w;
    #pragma unroll
    for (int o = 16; o; o >>= 1) ss += __shfl_xor_sync(0xffffffffu, ss, o);
    __shared__ float sred[8];
    if ((tid & 31) == 0) sred[tid >> 5] = ss;
    __syncthreads();
    float tot = 0.f;
    #pragma unroll
    for (int i = 0; i < 8; i++) tot += sred[i];
    const float sc = rsqrtf(tot * (1.f/1024.f) + 1e-6f);
    const float4 ww = *(const float4*)(w + tid*4);
    float4 r;
    r.x = rtf32(v.x*sc*ww.x); r.y = rtf32(v.y*sc*ww.y);
    r.z = rtf32(v.z*sc*ww.z); r.w = rtf32(v.w*sc*ww.w);
    *(float4*)(out + (size_t)row*HS + tid*4) = r;
}

// ----------------------- tf32 tensor-core GEMM (pipelined) -----------------
#define ASTR 20
#define BSTR 136
#define A_SZ (128*ASTR)
#define B_SZ (16*BSTR)
#define STAGES 3
#define GSMEM ((STAGES*(A_SZ + B_SZ))*4)    // 56832 bytes

template<int EPI>
__global__ __launch_bounds__(256, 2) void tgemm_k(const float* __restrict__ A,
                                                  const float* __restrict__ B,
                                                  float* __restrict__ C,
                                                  const float* __restrict__ X,
                                                  int M, int N, int K)
{
    extern __shared__ uint32_t dyn[];
    uint32_t* Abase = dyn;
    uint32_t* Bbase = dyn + STAGES*A_SZ;

    const int tid  = threadIdx.x;
    const int lane = tid & 31, wid = tid >> 5;
    const int wr = wid >> 2, wc = wid & 3;
    const int g = lane >> 2, kc = lane & 3;
    const int bx = blockIdx.x, by = blockIdx.y;

    const float* Ab = A + (size_t)by*128*K;
    const float* Bb = B + (size_t)bx*128;

    const int ar0 = tid >> 2, ac0 = (tid & 3)*4;
    const int br0 = tid >> 5, bc0 = (tid & 31)*4;

    const uint32_t sa0 = (uint32_t)__cvta_generic_to_shared(&Abase[ar0*ASTR + ac0]);
    const uint32_t sa1 = (uint32_t)__cvta_generic_to_shared(&Abase[(ar0+64)*ASTR + ac0]);
    const uint32_t sb0 = (uint32_t)__cvta_generic_to_shared(&Bbase[br0*BSTR + bc0]);
    const uint32_t sb1 = (uint32_t)__cvta_generic_to_shared(&Bbase[(br0+8)*BSTR + bc0]);

    const int NT = K >> 4;

    #define ISSUE(stg, kt)                                                     \
        do {                                                                   \
            const uint32_t ao = (stg)*A_SZ*4, bo = (stg)*B_SZ*4;               \
            cpa16(sa0 + ao, Ab + (size_t)ar0*K + (kt) + ac0);                  \
            cpa16(sa1 + ao, Ab + (size_t)(ar0+64)*K + (kt) + ac0);             \
            cpa16(sb0 + bo, Bb + (size_t)((kt)+br0)*N + bc0);                  \
            cpa16(sb1 + bo, Bb + (size_t)((kt)+br0+8)*N + bc0);                \
        } while (0)

    ISSUE(0, 0);  CPA_COMMIT();
    ISSUE(1, 16); CPA_COMMIT();

    float acc[4][4][4];
    #pragma unroll
    for (int i = 0; i < 4; i++)
        #pragma unroll
        for (int j = 0; j < 4; j++)
            #pragma unroll
            for (int t = 0; t < 4; t++) acc[i][j][t] = 0.f;

    int stage = 0;
    for (int i = 0; i < NT; i++) {
        CPA_WAIT1();
        __syncthreads();

        const int pf = i + 2;
        if (pf < NT) {
            const int ps = (stage + 2 >= STAGES) ? stage + 2 - STAGES : stage + 2;
            ISSUE(ps, pf*16);
        }
        CPA_COMMIT();

        const uint32_t* As = Abase + stage*A_SZ;
        const uint32_t* Bs = Bbase + stage*B_SZ;

        #pragma unroll
        for (int ks = 0; ks < 2; ks++) {
            const int k0 = ks*8;
            uint32_t af[4][4], bf[4][2];
            #pragma unroll
            for (int mi = 0; mi < 4; mi++) {
                const int m0 = wr*64 + mi*16;
                af[mi][0] = As[(m0+g  )*ASTR + k0+kc  ];
                af[mi][1] = As[(m0+g+8)*ASTR + k0+kc  ];
                af[mi][2] = As[(m0+g  )*ASTR + k0+kc+4];
                af[mi][3] = As[(m0+g+8)*ASTR + k0+kc+4];
            }
            #pragma unroll
            for (int nj = 0; nj < 4; nj++) {
                const int n0 = wc*32 + nj*8;
                bf[nj][0] = Bs[(k0+kc  )*BSTR + n0+g];
                bf[nj][1] = Bs[(k0+kc+4)*BSTR + n0+g];
            }
            #pragma unroll
            for (int mi = 0; mi < 4; mi++)
                #pragma unroll
                for (int nj = 0; nj < 4; nj++)
                    mma_tf32(acc[mi][nj], af[mi], bf[nj]);
        }
        stage = (stage + 1 >= STAGES) ? 0 : stage + 1;
    }
    #undef ISSUE

    // ------------------------------ epilogue -------------------------------
    const int cp = (lane & 3)*2;
    #pragma unroll
    for (int mi = 0; mi < 4; mi++) {
        #pragma unroll
        for (int rh = 0; rh < 2; rh++) {
            const size_t row = (size_t)by*128 + wr*64 + mi*16 + g + rh*8;
            #pragma unroll
            for (int nj = 0; nj < 4; nj++) {
                const size_t col = (size_t)bx*128 + wc*32 + nj*8 + cp;
                const size_t idx = row*N + col;
                float v0 = acc[mi][nj][rh*2+0];
                float v1 = acc[mi][nj][rh*2+1];
                if (EPI == 1) { v0 += X[idx]; v1 += X[idx+1]; }
                if (EPI == 2) {
                    float g0 = X[idx], g1 = X[idx+1];
                    v0 = rtf32(v0 * (g0 / (1.f + __expf(-g0))));
                    v1 = rtf32(v1 * (g1 / (1.f + __expf(-g1))));
                }
                float2 st; st.x = v0; st.y = v1;
                *(float2*)(C + idx) = st;
            }
        }
    }
}

// --------------------- glog = logsigmoid(h@Wgk1@Wgk2+b)/16 ------------------
__global__ __launch_bounds__(128) void glog_k(const float* __restrict__ h,
                                              const float* __restrict__ Wgk1,
                                              const float* __restrict__ Wgk2,
                                              const float* __restrict__ bg,
                                              float* __restrict__ glog)
{
    const int row = blockIdx.x, tid = threadIdx.x;
    float r[16];
    #pragma unroll
    for (int j = 0; j < 16; j++) r[j] = 0.f;
    const float* hp = h + (size_t)row*HS;
    for (int k2 = tid; k2 < HS; k2 += 128) {
        const float hv = hp[k2];
        const float4* wp = (const float4*)(Wgk1 + (size_t)k2*16);
        float4 w0 = wp[0], w1 = wp[1], w2 = wp[2], w3 = wp[3];
        r[0]+=hv*w0.x; r[1]+=hv*w0.y; r[2]+=hv*w0.z; r[3]+=hv*w0.w;
        r[4]+=hv*w1.x; r[5]+=hv*w1.y; r[6]+=hv*w1.z; r[7]+=hv*w1.w;
        r[8]+=hv*w2.x; r[9]+=hv*w2.y; r[10]+=hv*w2.z; r[11]+=hv*w2.w;
        r[12]+=hv*w3.x; r[13]+=hv*w3.y; r[14]+=hv*w3.z; r[15]+=hv*w3.w;
    }
    __shared__ float red[16*128];
    #pragma unroll
    for (int j = 0; j < 16; j++) red[j*128 + tid] = r[j];
    __syncthreads();
    for (int off = 64; off >= 1; off >>= 1) {
        if (tid < off) {
            #pragma unroll
            for (int j = 0; j < 16; j++) red[j*128+tid] += red[j*128+tid+off];
        }
        __syncthreads();
    }
    __shared__ float rs[16];
    if (tid < 16) rs[tid] = red[tid*128];
    __syncthreads();
    for (int d = tid; d < DK; d += 128) {
        float z = bg[d];
        #pragma unroll
        for (int j = 0; j < 16; j++) z += rs[j] * Wgk2[j*DK + d];
        const float ls = fminf(z, 0.f) - log1pf(__expf(-fabsf(z)));
        glog[(size_t)row*DK + d] = ls * (1.0f/16.0f);
    }
}

// -------------------- attention pass1: per (b,h,chunk) ----------------------
__global__ __launch_bounds__(256) void gla_pass1(
    const float* __restrict__ q, const float* __restrict__ k,
    const float* __restrict__ v, const float* __restrict__ glog,
    float* __restrict__ qe_out, float* __restrict__ o,
    float* __restrict__ dS, float* __restrict__ blast_out)
{
    extern __shared__ float sm1[];
    float* sb  = sm1;
    float* sqe = sb  + 64*STR1;
    float* ske = sqe + 64*STR1;
    float* sv  = ske + 64*STR1;
    float* sbl = sv  + 64*256;
    float* sA  = sb;

    const int c = blockIdx.x, hh = blockIdx.y, b = blockIdx.z;
    const int tid = threadIdx.x;
    const size_t tokbase = (size_t)b*2048 + (size_t)c*CHK;
    const float scale = 0.088388347648318447f;

    if (tid < 128) {
        const int d = tid;
        float run = 0.f;
        const float* gp = glog + tokbase*DK + hh*DKH + d;
        for (int i = 0; i < CHK; i++) {
            run += gp[(size_t)i*DK];
            sb[i*STR1 + d] = run;
        }
        sbl[d] = run;
    } else {
        const int t = tid - 128;
        const float* vp = v + tokbase*DV + hh*DVH;
        for (int idx = t; idx < 64*64; idx += 128) {
            const int i = idx >> 6, e4 = idx & 63;
            *(float4*)&sv[i*256 + e4*4] = *(const float4*)(vp + (size_t)i*DV + e4*4);
        }
    }
    __syncthreads();

    {
        const float* qp = q + tokbase*DK + hh*DKH;
        const float* kp = k + tokbase*DK + hh*DKH;
        float* qep = qe_out + tokbase*DK + hh*DKH;
        for (int idx = tid; idx < 64*128; idx += 256) {
            const int i = idx >> 7, d = idx & 127;
            const float bb = sb[i*STR1 + d];
            const float qe = qp[(size_t)i*DK + d] * __expf(bb) * scale;
            const float ke = kp[(size_t)i*DK + d] * __expf(-bb);
            sqe[i*STR1 + d] = qe;
            ske[i*STR1 + d] = ke;
            qep[(size_t)i*DK + d] = qe;
        }
    }
    __syncthreads();

    {
        const int tx = tid & 15, ty = tid >> 4;
        const int i0 = ty*4, j0 = tx*4;
        float acc[4][4] = {};
        for (int d = 0; d < 128; d++) {
            float a0[4], b0[4];
            #pragma unroll
            for (int ii = 0; ii < 4; ii++) a0[ii] = sqe[(i0+ii)*STR1 + d];
            #pragma unroll
            for (int jj = 0; jj < 4; jj++) b0[jj] = ske[(j0+jj)*STR1 + d];
            #pragma unroll
            for (int ii = 0; ii < 4; ii++)
                #pragma unroll
                for (int jj = 0; jj < 4; jj++)
                    acc[ii][jj] += a0[ii]*b0[jj];
        }
        #pragma unroll
        for (int ii = 0; ii < 4; ii++)
            #pragma unroll
            for (int jj = 0; jj < 4; jj++)
                sA[(i0+ii)*65 + j0+jj] = (j0+jj <= i0+ii) ? acc[ii][jj] : 0.f;
    }
    __syncthreads();

    {
        const int tx = tid & 15, ty = tid >> 4;
        const int i0 = ty*4, e0 = tx*16;
        float acc[4][16] = {};
        for (int j = 0; j < 64; j++) {
            float vv[16];
            #pragma unroll
            for (int q4 = 0; q4 < 4; q4++)
                *(float4*)&vv[q4*4] = *(const float4*)&sv[j*256 + e0 + q4*4];
            float aa[4];
            #pragma unroll
            for (int ii = 0; ii < 4; ii++) aa[ii] = sA[(i0+ii)*65 + j];
            #pragma unroll
            for (int ii = 0; ii < 4; ii++)
                #pragma unroll
                for (int jj = 0; jj < 16; jj++)
                    acc[ii][jj] += aa[ii]*vv[jj];
        }
        float* op = o + tokbase*DV + hh*DVH;
        #pragma unroll
        for (int ii = 0; ii < 4; ii++)
            #pragma unroll
            for (int jj = 0; jj < 16; jj++)
                op[(size_t)(i0+ii)*DV + e0 + jj] = acc[ii][jj];
    }

    {
        const int tx = tid & 15, ty = tid >> 4;
        const int d0 = ty*8;
        const size_t dbase = (((size_t)(b*NH + hh))*NCHK + c) * (DKH*DVH);
        #pragma unroll
        for (int half = 0; half < 2; half++) {
            const int e0 = tx*16 + half*8;
            float acc[8][8] = {};
            for (int i = 0; i < 64; i++) {
                float kk[8], vv[8];
                #pragma unroll
                for (int dd = 0; dd < 8; dd++) kk[dd] = ske[i*STR1 + d0 + dd];
                *(float4*)&vv[0] = *(const float4*)&sv[i*256 + e0];
                *(float4*)&vv[4] = *(const float4*)&sv[i*256 + e0 + 4];
                #pragma unroll
                for (int dd = 0; dd < 8; dd++)
                    #pragma unroll
                    for (int jj = 0; jj < 8; jj++)
                        acc[dd][jj] += kk[dd]*vv[jj];
            }
            #pragma unroll
            for (int dd = 0; dd < 8; dd++) {
                const float sc = __expf(sbl[d0+dd]);
                #pragma unroll
                for (int jj = 0; jj < 8; jj++)
                    dS[dbase + (size_t)(d0+dd)*DVH + e0 + jj] = acc[dd][jj]*sc;
            }
        }
    }
    if (tid < 128)
        blast_out[(((size_t)(b*NH + hh))*NCHK + c)*DKH + tid] = sbl[tid];
}

// ------- attention pass2: sequential scan, (b,h, dv-slice of 32) -----------
__global__ __launch_bounds__(256) void gla_pass2(
    const float* __restrict__ qe, const float* __restrict__ dS,
    const float* __restrict__ blast, float* __restrict__ o)
{
    extern __shared__ float sm2[];
    float* S   = sm2;
    float* sq  = S + 128*33;
    float* sbl = sq + 64*STR1;

    const int es = blockIdx.x;
    const int hh = blockIdx.y, b = blockIdx.z;
    const int tid = threadIdx.x;
    const size_t bh = (size_t)b*NH + hh;

    for (int idx = tid; idx < 128*33; idx += 256) S[idx] = 0.f;
    __syncthreads();

    for (int c = 0; c < NCHK; c++) {
        const size_t tokbase = (size_t)b*2048 + (size_t)c*CHK;
        const float* qp = qe + tokbase*DK + hh*DKH;
        for (int idx = tid; idx < 64*32; idx += 256) {
            const int i = idx >> 5, d4 = idx & 31;
            float4 qv = *(const float4*)(qp + (size_t)i*DK + d4*4);
            const int s = i*STR1 + d4*4;
            sq[s] = qv.x; sq[s+1] = qv.y; sq[s+2] = qv.z; sq[s+3] = qv.w;
        }
        if (tid < 128) sbl[tid] = blast[(bh*NCHK + c)*DKH + tid];
        __syncthreads();

        {
            const int tx = tid & 7, ty = tid >> 3;
            const int i0 = ty*2, e0 = tx*4;
            float acc[2][4] = {};
            for (int d = 0; d < 128; d++) {
                float s0[4];
                #pragma unroll
                for (int jj = 0; jj < 4; jj++) s0[jj] = S[d*33 + e0 + jj];
                const float q0 = sq[i0*STR1 + d];
                const float q1 = sq[(i0+1)*STR1 + d];
                #pragma unroll
                for (int jj = 0; jj < 4; jj++) {
                    acc[0][jj] += q0*s0[jj];
                    acc[1][jj] += q1*s0[jj];
                }
            }
            float* op = o + tokbase*DV + hh*DVH + es*32;
            #pragma unroll
            for (int ii = 0; ii < 2; ii++)
                #pragma unroll
                for (int jj = 0; jj < 4; jj++)
                    op[(size_t)(i0+ii)*DV + e0 + jj] += acc[ii][jj];
        }
        __syncthreads();

        {
            const size_t dbase = (bh*NCHK + c)*(size_t)(DKH*DVH) + es*32;
            for (int idx = tid; idx < 128*32; idx += 256) {
                const int d = idx >> 5, e = idx & 31;
                S[d*33 + e] = S[d*33 + e]*__expf(sbl[d]) + dS[dbase + (size_t)d*DVH + e];
            }
        }
        __syncthreads();
    }
}

// --------- output gating: og = rms(o, gnorm_w) * silu(g_out) ---------------
__global__ __launch_bounds__(64) void gate_k(const float* __restrict__ o,
                                             const float* __restrict__ gout,
                                             const float* __restrict__ gw,
                                             float* __restrict__ og)
{
    const int bid = blockIdx.x;
    const int tok = bid >> 2, hh = bid & 3;
    const int tid = threadIdx.x;
    const size_t base = (size_t)tok*DV + hh*DVH;

    const float4 x = *(const float4*)(o + base + tid*4);
    float ss = x.x*x.x + x.y*x.y + x.z*x.z + x.w*x.w;
    #pragma unroll
    for (int off = 16; off; off >>= 1) ss += __shfl_xor_sync(0xffffffffu, ss, off);
    __shared__ float s2[2];
    if ((tid & 31) == 0) s2[tid >> 5] = ss;
    __syncthreads();
    ss = s2[0] + s2[1];
    const float sc = rsqrtf(ss * (1.f/256.f) + 1e-6f);

    const float4 g = *(const float4*)(gout + base + tid*4);
    const float4 w = *(const float4*)(gw + tid*4);
    float4 r;
    r.x = rtf32(x.x*sc*w.x * (g.x / (1.f + __expf(-g.x))));
    r.y = rtf32(x.y*sc*w.y * (g.y / (1.f + __expf(-g.y))));
    r.z = rtf32(x.z*sc*w.z * (g.z / (1.f + __expf(-g.z))));
    r.w = rtf32(x.w*sc*w.w * (g.w / (1.f + __expf(-g.w))));
    *(float4*)(og + base + tid*4) = r;
}

// ------------------------------- launcher ----------------------------------
extern "C" void kernel_launch(void* const* d_in, const int* in_sizes, int n_in,
                              void* d_out, int out_size)
{
    const float* x       = (const float*)d_in[0];
    const float* attn_w  = (const float*)d_in[1];
    const float* Wq      = (const float*)d_in[2];
    const float* Wk      = (const float*)d_in[3];
    const float* Wv      = (const float*)d_in[4];
    const float* Wg      = (const float*)d_in[5];
    const float* Wgk1    = (const float*)d_in[6];
    const float* Wgk2    = (const float*)d_in[7];
    const float* bgk2    = (const float*)d_in[8];
    const float* gnormw  = (const float*)d_in[9];
    const float* Wo      = (const float*)d_in[10];
    const float* mlpnw   = (const float*)d_in[11];
    const float* Wgate   = (const float*)d_in[12];
    const float* Wup     = (const float*)d_in[13];
    const float* Wdown   = (const float*)d_in[14];
    float* out = (float*)d_out;

    float *p_h, *p_q, *p_k, *p_v, *p_glog, *p_gout, *p_o, *p_big, *p_dS, *p_bl;
    cudaGetSymbolAddress((void**)&p_h, g_h);
    cudaGetSymbolAddress((void**)&p_q, g_q);
    cudaGetSymbolAddress((void**)&p_k, g_k);
    cudaGetSymbolAddress((void**)&p_v, g_v);
    cudaGetSymbolAddress((void**)&p_glog, g_glog);
    cudaGetSymbolAddress((void**)&p_gout, g_gout);
    cudaGetSymbolAddress((void**)&p_o, g_o);
    cudaGetSymbolAddress((void**)&p_big, g_big);
    cudaGetSymbolAddress((void**)&p_dS, g_dS);
    cudaGetSymbolAddress((void**)&p_bl, g_bl);

    float* p_og   = p_o;
    float* p_x2   = p_gout;
    float* p_n    = p_h;
    float* p_gate = p_big;
    float* p_act  = p_big;

    // Weight staging inside g_dS (16M floats):
    //  - early weights: used by projection GEMMs, dead before pass1 writes dS
    //  - late weights: converted after pass2 consumed dS
    float* cWq    = p_dS;                         // 524288
    float* cWk    = p_dS + (size_t)HS*DK;         // 524288
    float* cWv    = p_dS + (size_t)2*HS*DK;       // 1048576
    float* cWg    = p_dS + (size_t)2*HS*DK + (size_t)HS*DV;
    float* cWo    = p_dS;                         // 1048576
    float* cWgate = p_dS + (size_t)DV*HS;                       // 2883584
    float* cWup   = p_dS + (size_t)DV*HS + (size_t)HS*II;
    float* cWdown = p_dS + (size_t)DV*HS + (size_t)2*HS*II;     // ends 9699328 < 16M

    const int SMEM1 = (3*64*STR1 + 64*256 + 128) * 4;
    const int SMEM2 = (128*33 + 64*STR1 + 128) * 4;
    cudaFuncSetAttribute(gla_pass1, cudaFuncAttributeMaxDynamicSharedMemorySize, SMEM1);
    cudaFuncSetAttribute(gla_pass2, cudaFuncAttributeMaxDynamicSharedMemorySize, SMEM2);
    cudaFuncSetAttribute(tgemm_k<0>, cudaFuncAttributeMaxDynamicSharedMemorySize, GSMEM);
    cudaFuncSetAttribute(tgemm_k<1>, cudaFuncAttributeMaxDynamicSharedMemorySize, GSMEM);
    cudaFuncSetAttribute(tgemm_k<2>, cudaFuncAttributeMaxDynamicSharedMemorySize, GSMEM);

    // 0a. early weight tf32 pre-round (into dS scratch)
    cvtw_k<<<HS*DK/1024, 256>>>(Wq, cWq);
    cvtw_k<<<HS*DK/1024, 256>>>(Wk, cWk);
    cvtw_k<<<HS*DV/1024, 256>>>(Wv, cWv);
    cvtw_k<<<HS*DV/1024, 256>>>(Wg, cWg);
    // 1. h = rmsnorm(x)  (tf32-rounded)
    rmsnorm_k<<<NTOK, 256>>>(x, attn_w, p_h);
    // 2. projections
    tgemm_k<0><<<dim3(DK/128, NTOK/128), 256, GSMEM>>>(p_h, cWq, p_q, nullptr, NTOK, DK, HS);
    tgemm_k<0><<<dim3(DK/128, NTOK/128), 256, GSMEM>>>(p_h, cWk, p_k, nullptr, NTOK, DK, HS);
    tgemm_k<0><<<dim3(DV/128, NTOK/128), 256, GSMEM>>>(p_h, cWv, p_v, nullptr, NTOK, DV, HS);
    tgemm_k<0><<<dim3(DV/128, NTOK/128), 256, GSMEM>>>(p_h, cWg, p_gout, nullptr, NTOK, DV, HS);
    // 3. gate logits
    glog_k<<<NTOK, 128>>>(p_h, Wgk1, Wgk2, bgk2, p_glog);
    // 4. attention (pass1 overwrites dS — early weight copies now dead)
    gla_pass1<<<dim3(NCHK, NH, 4), 256, SMEM1>>>(p_q, p_k, p_v, p_glog,
                                                 p_q, p_o, p_dS, p_bl);
    gla_pass2<<<dim3(8, NH, 4), 256, SMEM2>>>(p_q, p_dS, p_bl, p_o);
    // 5. output gating (in-place)
    gate_k<<<NTOK*NH, 64>>>(p_o, p_gout, gnormw, p_og);
    // 0b. late weight tf32 pre-round (dS consumed by pass2)
    cvtw_k<<<DV*HS/1024, 256>>>(Wo, cWo);
    cvtw_k<<<HS*II/1024, 256>>>(Wgate, cWgate);
    cvtw_k<<<HS*II/1024, 256>>>(Wup, cWup);
    cvtw_k<<<II*HS/1024, 256>>>(Wdown, cWdown);
    // 6. x2 = og @ Wo + x
    tgemm_k<1><<<dim3(HS/128, NTOK/128), 256, GSMEM>>>(p_og, cWo, p_x2, x, NTOK, HS, DV);
    // 7. MLP
    rmsnorm_k<<<NTOK, 256>>>(p_x2, mlpnw, p_n);
    tgemm_k<0><<<dim3(II/128, NTOK/128), 256, GSMEM>>>(p_n, cWgate, p_gate, nullptr, NTOK, II, HS);
    tgemm_k<2><<<dim3(II/128, NTOK/128), 256, GSMEM>>>(p_n, cWup, p_act, p_gate, NTOK, II, HS);
    tgemm_k<1><<<dim3(HS/128, NTOK/128), 256, GSMEM>>>(p_act, cWdown, out, p_x2, NTOK, HS, II);
}